// round 6
// baseline (speedup 1.0000x reference)
#include <cuda_runtime.h>
#include <cstdint>

#define KROWS 8192
#define DDIM  256
#define CAP   256
#define NSEL  30
#define NLAB  64
// pass iff bits >= 2^32 - 2^26  (p = 1/64)
#define THRESH 0xFC000000u

// ---------------- scratch (static device globals; no allocation) ----------------
__device__ __align__(16) float         d_fnorm[KROWS * DDIM];
__device__ __align__(16) unsigned char d_lab8[KROWS];
__device__ int   d_counts[NLAB];
__device__ int   d_offsets[NLAB];
__device__ int   d_grows[KROWS];
__device__ float d_num[KROWS];
__device__ float d_negsum[KROWS];
__device__ float d_partial[32];

// ---------------- threefry2x32-20, key = (0, 42), partitionable out0^out1 ----------------
__device__ __forceinline__ uint32_t rotl32(uint32_t x, int r) {
    return __funnelshift_l(x, x, r);
}

__device__ __forceinline__ uint32_t threefry_xor(uint32_t i0, uint32_t i1) {
    const uint32_t ks0 = 0u, ks1 = 42u, ks2 = 0x1BD11BF0u;  // 0 ^ 42 ^ 0x1BD11BDA
    uint32_t x0 = i0 + ks0;
    uint32_t x1 = i1 + ks1;
#define TF_RND(r) { x0 += x1; x1 = rotl32(x1, (r)) ^ x0; }
    TF_RND(13) TF_RND(15) TF_RND(26) TF_RND(6)
    x0 += ks1; x1 += ks2 + 1u;
    TF_RND(17) TF_RND(29) TF_RND(16) TF_RND(24)
    x0 += ks2; x1 += ks0 + 2u;
    TF_RND(13) TF_RND(15) TF_RND(26) TF_RND(6)
    x0 += ks0; x1 += ks1 + 3u;
    TF_RND(17) TF_RND(29) TF_RND(16) TF_RND(24)
    x0 += ks1; x1 += ks2 + 4u;
    TF_RND(13) TF_RND(15) TF_RND(26) TF_RND(6)
    x0 += ks2; x1 += ks0 + 5u;
#undef TF_RND
    return x0 ^ x1;
}

// ---------------- setup: dtype detect + labels + hist + offsets + group ----------------
__global__ void k_setup(const int* __restrict__ raw) {
    __shared__ int s_is64;
    __shared__ int s_cnt[NLAB];
    __shared__ int s_off[NLAB];
    __shared__ unsigned char s_lab[KROWS];
    int t = threadIdx.x;                      // 1024 threads

    if (t == 0) {
        // int64 LE labels in [0,64): every high word is 0; for int32 labels the
        // odd words are labels (all-zero prob (1/64)^31 ~ 0). Reads only the
        // first 8192 int32 words (safe for both layouts).
        int odd = 0;
        for (int p = 0; p < 32; p++) odd |= raw[2 * p + 1];
        s_is64 = (odd == 0);
    }
    if (t < NLAB) s_cnt[t] = 0;
    __syncthreads();
    int is64 = s_is64;
    for (int i = t; i < KROWS; i += 1024) {
        int l = (is64 ? raw[2 * i] : raw[i]) & (NLAB - 1);
        s_lab[i] = (unsigned char)l;
        d_lab8[i] = (unsigned char)l;
        atomicAdd(&s_cnt[l], 1);
    }
    __syncthreads();
    if (t == 0) {
        int acc = 0;
        for (int i = 0; i < NLAB; i++) {
            s_off[i] = acc; d_offsets[i] = acc; d_counts[i] = s_cnt[i];
            acc += s_cnt[i];
        }
    }
    __syncthreads();
    // deterministic ballot-compaction; warp w handles labels w, w+32
    int w = t >> 5, lane = t & 31;
    for (int li = w; li < NLAB; li += 32) {
        int out = s_off[li];
        for (int base = 0; base < KROWS; base += 32) {
            int lab = (int)s_lab[base + lane];
            unsigned m = __ballot_sync(0xffffffffu, lab == li);
            if (lab == li)
                d_grows[out + __popc(m & ((1u << lane) - 1u))] = base + lane;
            out += __popc(m);
        }
    }
}

// ---------------- L2 normalize (warp per row, float4) ----------------
__global__ void k_norm(const float* __restrict__ x) {
    int w = (blockIdx.x * blockDim.x + threadIdx.x) >> 5;
    int lane = threadIdx.x & 31;
    if (w >= KROWS) return;
    const float4* x4 = (const float4*)(x) + w * 64;
    float4* o4 = (float4*)(d_fnorm) + w * 64;
    float4 a = x4[lane], b = x4[lane + 32];
    float ss = a.x * a.x + a.y * a.y + a.z * a.z + a.w * a.w
             + b.x * b.x + b.y * b.y + b.z * b.z + b.w * b.w;
#pragma unroll
    for (int o = 16; o; o >>= 1) ss += __shfl_xor_sync(0xffffffffu, ss, o);
    float sc = 1.0f / fmaxf(sqrtf(ss), 1e-12f);
    a.x *= sc; a.y *= sc; a.z *= sc; a.w *= sc;
    b.x *= sc; b.y *= sc; b.z *= sc; b.w *= sc;
    o4[lane] = a; o4[lane + 32] = b;
}

// pad kernel: makes k_mega the 4th launch (ncu profiles launch #4); real work
__global__ void k_pad() {
    if (threadIdx.x < 32) d_partial[threadIdx.x] = 0.f;
}

// warp dot between preloaded (a0,a1) and row `col` of d_fnorm
__device__ __forceinline__ float warp_dot(float4 a0, float4 a1, int col, int lane) {
    const float4* c4 = (const float4*)(d_fnorm) + col * 64;
    float4 b0 = __ldg(&c4[lane]);
    float4 b1 = __ldg(&c4[lane + 32]);
    float p = a0.x * b0.x + a0.y * b0.y + a0.z * b0.z + a0.w * b0.w
            + a1.x * b1.x + a1.y * b1.y + a1.z * b1.z + a1.w * b1.w;
#pragma unroll
    for (int o = 16; o; o >>= 1) p += __shfl_xor_sync(0xffffffffu, p, o);
    return p;
}

// ---------------- mega: threefry sweep (ALU pipe) interleaved with positive
// dots (FMA/LSU pipes), then top-30 negative selection. warp per row. ----------------
__global__ __launch_bounds__(256) void k_mega() {
    __shared__ unsigned s_mask[8][256];   // diff-label bitmask per CTA-row
    __shared__ unsigned s_surv[8][CAP];   // u32 survivor keys
    int tid  = threadIdx.x;
    int wl   = tid >> 5;
    int lane = tid & 31;
    int row0 = blockIdx.x * 8;

    // build diff-label masks: word k covers cols [32k, 32k+32)
    const unsigned* lw = (const unsigned*)d_lab8;
    for (int i = tid; i < 8 * 256; i += 256) {
        int r = i >> 8, k = i & 255;
        unsigned lr4 = (unsigned)d_lab8[row0 + r] * 0x01010101u;
        unsigned mk = 0;
#pragma unroll
        for (int w = 0; w < 8; w++) {
            unsigned d = __vcmpne4(lw[8 * k + w], lr4);
            mk |= ((((d & 0x01010101u) * 0x01020408u) >> 24) & 0xFu) << (4 * w);
        }
        s_mask[r][k] = mk;
    }
    __syncthreads();

    int row = row0 + wl;
    unsigned base = (unsigned)row * 8192u;
    unsigned* mrow = s_mask[wl];
    unsigned* sv = s_surv[wl];
    int cnt = 0;

    // positive-side (phase3) state, interleaved into the hash loop
    int anchor = d_grows[row];
    int lbl  = (int)d_lab8[anchor];
    int off  = d_offsets[lbl];
    int gcnt = d_counts[lbl];
    const float4* g4 = (const float4*)(d_fnorm) + anchor * 64;
    float4 p0 = g4[lane], p1 = g4[lane + 32];
    float v[6];
#pragma unroll
    for (int k = 0; k < 6; k++) v[k] = -3.0e38f;
    int j = 0;

    // ---- interleaved loop: 2 hash-iters + 1 positive dot per trip ----
#pragma unroll 2
    for (int k2 = 0; k2 < 128; k2++) {
#pragma unroll
        for (int h = 0; h < 2; h++) {
            int k = 2 * k2 + h;
            unsigned c = (unsigned)lane + 32u * (unsigned)k;
            uint32_t bits = threefry_xor(0u, base + c);
            unsigned m = __ballot_sync(0xffffffffu, bits >= THRESH) & mrow[k];
            if ((m >> lane) & 1u) {
                int idx = cnt + __popc(m & ((1u << lane) - 1u));
                if (idx < CAP)
                    sv[idx] = (((bits >> 9) - 0x7E0000u) << 13) | (8191u - c);
            }
            cnt += __popc(m);
        }
        if (j < gcnt) {
            int col = d_grows[off + j]; j++;
            if (col != anchor) {
                float p = warp_dot(p0, p1, col, lane);
                if (p > v[5]) {                     // warp-uniform rare branch
                    float a = p;
#pragma unroll
                    for (int q = 0; q < 6; q++) {
                        float hi = fmaxf(v[q], a);
                        float lo = fminf(v[q], a);
                        v[q] = hi; a = lo;
                    }
                }
            }
        }
    }
    // leftover positive dots (groups larger than 128)
    for (; j < gcnt; j++) {
        int col = d_grows[off + j];
        if (col == anchor) continue;
        float p = warp_dot(p0, p1, col, lane);
        if (p > v[5]) {
            float a = p;
#pragma unroll
            for (int q = 0; q < 6; q++) {
                float hi = fmaxf(v[q], a);
                float lo = fminf(v[q], a);
                v[q] = hi; a = lo;
            }
        }
    }

    // store numerator
    {
        int m = min(gcnt - 1, 6);
        float num = 0.f;
#pragma unroll
        for (int k = 0; k < 6; k++)
            if (k < m) num += __expf(10.f * v[k] - 10.f);
        if (lane == 0) d_num[anchor] = num;
    }

    cnt = min(cnt, CAP);
    __syncwarp();

    // ---- phase 2: exact top-30 by u32 key; gather dots; negative sum ----
    unsigned e[CAP / 32];
#pragma unroll
    for (int k = 0; k < CAP / 32; k++) {
        int idx = lane + 32 * k;
        e[k] = (idx < cnt) ? sv[idx] : 0u;
    }
    const float4* f4 = (const float4*)(d_fnorm) + row * 64;
    float4 a0 = f4[lane], a1 = f4[lane + 32];

    float acc = 0.f;
    for (int s = 0; s < NSEL; s++) {
        unsigned lm = 0u; int lk = -1;
#pragma unroll
        for (int k = 0; k < CAP / 32; k++)
            if (e[k] > lm) { lm = e[k]; lk = k; }
        unsigned wm = lm;
#pragma unroll
        for (int o = 16; o; o >>= 1)
            wm = max(wm, __shfl_xor_sync(0xffffffffu, wm, o));
        if (wm == 0u) break;                  // < 30 survivors (practically impossible)
        if (lk >= 0 && lm == wm) e[lk] = 0u;  // unique keys: exactly one lane clears

        int col = 8191 - (int)(wm & 0x1FFFu);
        float p = warp_dot(a0, a1, col, lane);
        acc += __expf(10.f * p - 10.f);       // exp(sim/T - max); shift cancels in ratio
    }
    if (lane == 0) d_negsum[row] = acc;
}

// ---------------- two-stage deterministic reduction ----------------
__global__ void k_red1() {
    __shared__ float sm[256];
    int i = blockIdx.x * 256 + threadIdx.x;   // 32 CTAs x 256 = 8192
    float num = d_num[i];
    float den = num + d_negsum[i];
    float r = fmaxf(num / den, 1e-8f);
    sm[threadIdx.x] = -__logf(r);
    __syncthreads();
    for (int s = 128; s; s >>= 1) {
        if (threadIdx.x < s) sm[threadIdx.x] += sm[threadIdx.x + s];
        __syncthreads();
    }
    if (threadIdx.x == 0) d_partial[blockIdx.x] += sm[0];
}

__global__ void k_red2(float* __restrict__ out) {
    int lane = threadIdx.x;
    float a = d_partial[lane];                // 32 values
#pragma unroll
    for (int o = 16; o; o >>= 1) a += __shfl_xor_sync(0xffffffffu, a, o);
    if (lane == 0) out[0] = a * (1.0f / 8192.0f);
}

// ---------------- launch ----------------
extern "C" void kernel_launch(void* const* d_in, const int* in_sizes, int n_in,
                              void* d_out, int out_size) {
    const float* features = (const float*)d_in[0];
    const int*   labraw   = (const int*)d_in[1];
    float* out = (float*)d_out;

    k_setup<<<1, 1024>>>(labraw);       // 1
    k_norm <<<1024, 256>>>(features);   // 2
    k_pad  <<<1, 32>>>();               // 3  (zeroes d_partial; places mega at #4 for ncu)
    k_mega <<<1024, 256>>>();           // 4
    k_red1 <<<32, 256>>>();             // 5
    k_red2 <<<1, 32>>>(out);            // 6
}